// round 14
// baseline (speedup 1.0000x reference)
#include <cuda_runtime.h>
#include <math.h>

#define BB 32
#define TT 512
#define DD 768
#define WW 255
#define HH 768
#define G4 3072           // 4*H
#define MR (BB*WW)        // 8160
#define MPAD 8192
#define NNER 9

// persistent LSTM kernel config
#define UPB 12            // hidden units per block
#define CPB 48            // gate columns per block (4*UPB)
#define NBD 64            // blocks per direction
#define NBLK (2*NBD)      // 128 total
#define NW 16             // warps per block
#define KPW 48            // k rows per warp (HH/16)
#define SC  4             // k rows per sub-chunk
#define NSC (KPW/SC)      // 12 sub-chunks
#define GPITCH 50         // gred row pitch
#define GWSZ (BB*GPITCH)  // per-slot gred region (1600 floats)

// ---------------- scratch ----------------
__device__ int   g_fidx[MR];
__device__ float g_pooled[MPAD*DD];
__device__ float g_xg[2][(size_t)MPAD*G4];
__device__ float g_hstate[2][2][HH][BB];   // [buf][dir][k][m]
__device__ float g_hs[2][(size_t)MR*HH];
__device__ int   g_flag[2][NBD];           // per-block step counters

typedef unsigned long long ull;
struct __align__(16) ull2 { ull x, y; };

__device__ __forceinline__ void ffma2(ull &c, ull a, ull b){
    asm("fma.rn.f32x2 %0, %1, %2, %0;" : "+l"(c) : "l"(a), "l"(b));
}
__device__ __forceinline__ ull add2(ull a, ull b){
    ull r; asm("add.rn.f32x2 %0, %1, %2;" : "=l"(r) : "l"(a), "l"(b)); return r;
}
__device__ __forceinline__ ull splat2(float x){
    ull r; asm("mov.b64 %0, {%1, %1};" : "=l"(r) : "f"(x)); return r;
}
__device__ __forceinline__ float2 unpack2(ull v){
    float2 f; asm("mov.b64 {%0, %1}, %2;" : "=f"(f.x), "=f"(f.y) : "l"(v)); return f;
}
__device__ __forceinline__ float sigmoidf_(float x){ return 1.0f/(1.0f + expf(-x)); }
// volatile poll load — cannot be hoisted out of the spin loop
__device__ __forceinline__ int ld_poll(const int* p){
    int v; asm volatile("ld.global.cg.b32 %0, [%1];" : "=r"(v) : "l"(p) : "memory");
    return v;
}
// pack a float4 of h values into 4 duplicated (h,h) ull pairs at dst (16B aligned)
__device__ __forceinline__ void pack_store(ull* dst, float4 v){
    ull2 a, b;
    a.x = splat2(v.x); a.y = splat2(v.y);
    b.x = splat2(v.z); b.y = splat2(v.w);
    ((ull2*)dst)[0] = a;
    ((ull2*)dst)[1] = b;
}

// ---------------- init ----------------
__global__ void k_init(){
    int i  = blockIdx.x*blockDim.x + threadIdx.x;
    int nt = gridDim.x*blockDim.x;
    for (int j=i; j<MR; j+=nt) g_fidx[j] = 0x7fffffff;
    for (int j=i; j<2*HH*BB; j+=nt) (&g_hstate[0][0][0][0])[j] = 0.f;   // buf0, both dirs
    for (int j=i; j<2*NBD; j+=nt) (&g_flag[0][0])[j] = 0;
    for (int j=i; j<(MPAD-MR)*DD; j+=nt) g_pooled[(size_t)MR*DD + j] = 0.f;
}

// ---------------- first-subword index ----------------
__global__ void k_find(const int* __restrict__ wid){
    int i = blockIdx.x*blockDim.x + threadIdx.x;
    if (i < BB*TT){
        int w = wid[i];
        if (w >= 0 && w < WW) atomicMin(&g_fidx[(i/TT)*WW + w], i % TT);
    }
}

// ---------------- gather pooled rows ----------------
__global__ void k_gather(const float* __restrict__ bert){
    int p   = blockIdx.x;
    int idx = g_fidx[p];
    if (idx >= TT) idx = 0;
    int b = p / WW;
    const float4* src = (const float4*)(bert + ((size_t)b*TT + idx)*DD);
    float4*       dst = (float4*)(g_pooled + (size_t)p*DD);
    dst[threadIdx.x] = src[threadIdx.x];
}

// ---------------- input-gate GEMM (double-buffered, packed A) ----------------
__global__ __launch_bounds__(256, 2) void k_gemm_xg(
    const float* __restrict__ Wf, const float* __restrict__ Wb,
    const float* __restrict__ bf, const float* __restrict__ bbv)
{
    const float* Wm   = blockIdx.z ? Wb  : Wf;
    const float* bias = blockIdx.z ? bbv : bf;
    float* C = g_xg[blockIdx.z];

    __shared__ ull   As2[2][16][128];   // packed (a,a) pairs  32768 B
    __shared__ float Bs [2][16][128];   //                     16384 B

    int tid = threadIdx.x;
    int m0 = blockIdx.y*128, n0 = blockIdx.x*128;
    int tm  = (tid>>4)*8;
    int tn2 = (tid&15)*2;

    ull acc[8][4];
    #pragma unroll
    for (int i=0;i<8;i++){ acc[i][0]=0ull; acc[i][1]=0ull; acc[i][2]=0ull; acc[i][3]=0ull; }

    int r   = tid>>1;
    int kqa = (tid&1)*8;
    const float* Ag = g_pooled + (size_t)(m0+r)*DD + kqa;
    const float* Bg = Wm       + (size_t)(n0+r)*DD + kqa;

    float4 a0 = *(const float4*)(Ag);
    float4 a1 = *(const float4*)(Ag + 4);
    float4 b0 = *(const float4*)(Bg);
    float4 b1 = *(const float4*)(Bg + 4);
    As2[0][kqa+0][r]=splat2(a0.x); As2[0][kqa+1][r]=splat2(a0.y);
    As2[0][kqa+2][r]=splat2(a0.z); As2[0][kqa+3][r]=splat2(a0.w);
    As2[0][kqa+4][r]=splat2(a1.x); As2[0][kqa+5][r]=splat2(a1.y);
    As2[0][kqa+6][r]=splat2(a1.z); As2[0][kqa+7][r]=splat2(a1.w);
    Bs[0][kqa+0][r]=b0.x; Bs[0][kqa+1][r]=b0.y; Bs[0][kqa+2][r]=b0.z; Bs[0][kqa+3][r]=b0.w;
    Bs[0][kqa+4][r]=b1.x; Bs[0][kqa+5][r]=b1.y; Bs[0][kqa+6][r]=b1.z; Bs[0][kqa+7][r]=b1.w;
    __syncthreads();

    for (int kt=0; kt<48; kt++){
        int cur = kt & 1;
        if (kt < 47){
            int ko = (kt+1)*16;
            a0 = *(const float4*)(Ag + ko);
            a1 = *(const float4*)(Ag + ko + 4);
            b0 = *(const float4*)(Bg + ko);
            b1 = *(const float4*)(Bg + ko + 4);
        }
        #pragma unroll
        for (int kk=0; kk<16; kk++){
            const ull2* ap = (const ull2*)&As2[cur][kk][tm];
            ull2 a01 = ap[0], a23 = ap[1], a45 = ap[2], a67 = ap[3];
            ull bp0 = *(const ull*)&Bs[cur][kk][tn2];
            ull bp1 = *(const ull*)&Bs[cur][kk][tn2+32];
            ull bp2 = *(const ull*)&Bs[cur][kk][tn2+64];
            ull bp3 = *(const ull*)&Bs[cur][kk][tn2+96];
            ffma2(acc[0][0],a01.x,bp0); ffma2(acc[0][1],a01.x,bp1); ffma2(acc[0][2],a01.x,bp2); ffma2(acc[0][3],a01.x,bp3);
            ffma2(acc[1][0],a01.y,bp0); ffma2(acc[1][1],a01.y,bp1); ffma2(acc[1][2],a01.y,bp2); ffma2(acc[1][3],a01.y,bp3);
            ffma2(acc[2][0],a23.x,bp0); ffma2(acc[2][1],a23.x,bp1); ffma2(acc[2][2],a23.x,bp2); ffma2(acc[2][3],a23.x,bp3);
            ffma2(acc[3][0],a23.y,bp0); ffma2(acc[3][1],a23.y,bp1); ffma2(acc[3][2],a23.y,bp2); ffma2(acc[3][3],a23.y,bp3);
            ffma2(acc[4][0],a45.x,bp0); ffma2(acc[4][1],a45.x,bp1); ffma2(acc[4][2],a45.x,bp2); ffma2(acc[4][3],a45.x,bp3);
            ffma2(acc[5][0],a45.y,bp0); ffma2(acc[5][1],a45.y,bp1); ffma2(acc[5][2],a45.y,bp2); ffma2(acc[5][3],a45.y,bp3);
            ffma2(acc[6][0],a67.x,bp0); ffma2(acc[6][1],a67.x,bp1); ffma2(acc[6][2],a67.x,bp2); ffma2(acc[6][3],a67.x,bp3);
            ffma2(acc[7][0],a67.y,bp0); ffma2(acc[7][1],a67.y,bp1); ffma2(acc[7][2],a67.y,bp2); ffma2(acc[7][3],a67.y,bp3);
        }
        if (kt < 47){
            int nx = 1 - cur;
            As2[nx][kqa+0][r]=splat2(a0.x); As2[nx][kqa+1][r]=splat2(a0.y);
            As2[nx][kqa+2][r]=splat2(a0.z); As2[nx][kqa+3][r]=splat2(a0.w);
            As2[nx][kqa+4][r]=splat2(a1.x); As2[nx][kqa+5][r]=splat2(a1.y);
            As2[nx][kqa+6][r]=splat2(a1.z); As2[nx][kqa+7][r]=splat2(a1.w);
            Bs[nx][kqa+0][r]=b0.x; Bs[nx][kqa+1][r]=b0.y; Bs[nx][kqa+2][r]=b0.z; Bs[nx][kqa+3][r]=b0.w;
            Bs[nx][kqa+4][r]=b1.x; Bs[nx][kqa+5][r]=b1.y; Bs[nx][kqa+6][r]=b1.z; Bs[nx][kqa+7][r]=b1.w;
            __syncthreads();
        }
    }

    #pragma unroll
    for (int i=0;i<8;i++){
        float* crow = C + (size_t)(m0+tm+i)*G4 + n0;
        #pragma unroll
        for (int j=0;j<4;j++){
            float2 v = unpack2(acc[i][j]);
            v.x += bias[n0+tn2+32*j];
            v.y += bias[n0+tn2+32*j+1];
            *(float2*)(crow + tn2 + 32*j) = v;
        }
    }
}

// ---------------- persistent bidirectional LSTM ----------------
// 128 blocks x 512 threads (16 warps, 4/SMSP), 1 block/SM via ~226KB smem.
// Warp w owns k rows [w*48, (w+1)*48), staged warp-privately from global in
// 4-row double-buffered sub-chunks as PRE-PACKED (h,h) ull pairs (splats at
// staging, not in the inner loop). Lane = cg(8) x mh(4); 8m x 6c per lane.
// Reduction: warps 8-15 dump -> warps 0-7 fold partner -> cell sums 8 slots.
__global__ __launch_bounds__(512, 1) void k_lstm_pers(
    const float* __restrict__ Whf, const float* __restrict__ Whb)
{
    extern __shared__ float sm[];
    float* ws   = sm;                              // [768][48]     147456 B
    ull*   hb   = (ull*)(sm + HH*CPB);             // 16 warps x 256 ull = 32768 B
    float* gred = sm + HH*CPB + 8192;              // [8][32][50]    51200 B

    int tid = threadIdx.x;
    int bid = blockIdx.x;
    int d    = bid >> 6;
    int bid6 = bid & 63;
    int u0   = bid6 * UPB;
    const float* Wm = d ? Whb : Whf;
    int* flagd = g_flag[d];

    // stage weights: ws[k][c], c = g*UPB+uu
    for (int idx = tid; idx < CPB*(HH/4); idx += 512){
        int c  = idx / (HH/4);
        int kq = (idx % (HH/4)) * 4;
        int g = c / UPB, uu = c % UPB;
        float4 w = *(const float4*)(Wm + (size_t)(g*HH + u0 + uu)*HH + kq);
        ws[(kq+0)*CPB + c] = w.x;
        ws[(kq+1)*CPB + c] = w.y;
        ws[(kq+2)*CPB + c] = w.z;
        ws[(kq+3)*CPB + c] = w.w;
    }
    __syncthreads();

    int warp  = tid >> 5;
    int lane  = tid & 31;
    int mh    = lane >> 3;
    int cBase = (lane & 7) * 6;

    ull* hbw = hb + warp*256;                 // 2 bufs x 4 rows x 32 ull
    int  kwq4 = warp*KPW*8;                   // warp k-base in float4 units
    // staging: lane stages float4 (row=lane>>3, q=lane&7) -> 4 packed ull
    ull* spack = hbw + (lane>>3)*32 + (lane&7)*4;

    const float* xg_d = g_xg[d];
    int uu1 = tid >> 5, mm1 = tid & 31;       // cell pair (tid<384)
    float c1 = 0.f;

    for (int s = 0; s < WW; s++){
        int t = d ? (WW-1-s) : s;
        const float4* hs4 = (const float4*)(&g_hstate[s&1][d][0][0]) + kwq4;
        float*        hdst = &g_hstate[(s+1)&1][d][0][0];

        // xg prefetch for cell phase
        float x1[4];
        if (tid < 384){
            const float* xb = xg_d + (size_t)(mm1*WW + t)*G4 + u0 + uu1;
            x1[0]=xb[0]; x1[1]=xb[HH]; x1[2]=xb[2*HH]; x1[3]=xb[3*HH];
        }

        // stage sub-chunk 0 (warp-private; L1 bypass: h written by remote SMs)
        float4 p0 = __ldcg(hs4 + lane);
        pack_store(spack, p0);
        __syncwarp();

        ull acc[8][3];
        #pragma unroll
        for (int mi=0;mi<8;mi++){ acc[mi][0]=0ull; acc[mi][1]=0ull; acc[mi][2]=0ull; }

        for (int sc=0; sc<NSC; sc++){
            int cur = sc & 1;
            if (sc < NSC-1){
                p0 = __ldcg(hs4 + (sc+1)*32 + lane);
            }
            const ull*   hc = hbw + cur*128 + mh*8;
            const float* wc = ws + (warp*KPW + sc*SC)*CPB + cBase;
            #pragma unroll
            for (int r=0; r<SC; r++){
                const ull2* hp = (const ull2*)(hc + r*32);
                ull2 h01 = hp[0], h23 = hp[1], h45 = hp[2], h67 = hp[3];
                ull w0 = *(const ull*)(wc + r*CPB);
                ull w1 = *(const ull*)(wc + r*CPB + 2);
                ull w2 = *(const ull*)(wc + r*CPB + 4);
                ffma2(acc[0][0],h01.x,w0); ffma2(acc[0][1],h01.x,w1); ffma2(acc[0][2],h01.x,w2);
                ffma2(acc[1][0],h01.y,w0); ffma2(acc[1][1],h01.y,w1); ffma2(acc[1][2],h01.y,w2);
                ffma2(acc[2][0],h23.x,w0); ffma2(acc[2][1],h23.x,w1); ffma2(acc[2][2],h23.x,w2);
                ffma2(acc[3][0],h23.y,w0); ffma2(acc[3][1],h23.y,w1); ffma2(acc[3][2],h23.y,w2);
                ffma2(acc[4][0],h45.x,w0); ffma2(acc[4][1],h45.x,w1); ffma2(acc[4][2],h45.x,w2);
                ffma2(acc[5][0],h45.y,w0); ffma2(acc[5][1],h45.y,w1); ffma2(acc[5][2],h45.y,w2);
                ffma2(acc[6][0],h67.x,w0); ffma2(acc[6][1],h67.x,w1); ffma2(acc[6][2],h67.x,w2);
                ffma2(acc[7][0],h67.y,w0); ffma2(acc[7][1],h67.y,w1); ffma2(acc[7][2],h67.y,w2);
            }
            if (sc < NSC-1){
                pack_store(hbw + (1-cur)*128 + (lane>>3)*32 + (lane&7)*4, p0);
            }
            __syncwarp();
        }

        // reduction phase 1: warps 8-15 dump partials to gred[warp-8]
        if (warp >= 8){
            float* gr = gred + (warp-8)*GWSZ + mh*8*GPITCH + cBase;
            #pragma unroll
            for (int mi=0;mi<8;mi++){
                float* row = gr + mi*GPITCH;
                *(float2*)(row    ) = unpack2(acc[mi][0]);
                *(float2*)(row + 2) = unpack2(acc[mi][1]);
                *(float2*)(row + 4) = unpack2(acc[mi][2]);
            }
        }
        __syncthreads();

        // phase 2: warps 0-7 fold partner (warp+8) partials, dump 2-way sums
        if (warp < 8){
            float* gr = gred + warp*GWSZ + mh*8*GPITCH + cBase;
            #pragma unroll
            for (int mi=0;mi<8;mi++){
                float* row = gr + mi*GPITCH;
                ull v0 = add2(acc[mi][0], *(const ull*)(row    ));
                ull v1 = add2(acc[mi][1], *(const ull*)(row + 2));
                ull v2 = add2(acc[mi][2], *(const ull*)(row + 4));
                *(float2*)(row    ) = unpack2(v0);
                *(float2*)(row + 2) = unpack2(v1);
                *(float2*)(row + 4) = unpack2(v2);
            }
        }
        __syncthreads();

        // LSTM cell: sum 8 slots + xg (tid<384: one (u,m) pair each)
        if (tid < 384){
            int base = mm1*GPITCH + uu1;
            float gi=x1[0], gf=x1[1], gg=x1[2], go=x1[3];
            #pragma unroll
            for (int w=0; w<8; w++){
                const float* g = gred + w*GWSZ + base;
                gi += g[0]; gf += g[UPB]; gg += g[2*UPB]; go += g[3*UPB];
            }
            float cn = sigmoidf_(gf)*c1 + sigmoidf_(gi)*tanhf(gg);
            float h  = sigmoidf_(go)*tanhf(cn);
            c1 = cn;
            hdst[(u0+uu1)*BB + mm1] = h;
            g_hs[d][(size_t)(mm1*WW + t)*HH + u0 + uu1] = h;
        }

        // inter-block barrier: per-block flag + poll-all (volatile loads)
        __threadfence();
        __syncthreads();
        if (tid == 0) atomicExch(&flagd[bid6], s+1);
        if (tid < 32){
            int tgt = s + 1;
            while (true){
                int a = ld_poll(&flagd[tid]);
                int b = ld_poll(&flagd[tid+32]);
                if (__all_sync(0xffffffffu, (a >= tgt) && (b >= tgt))) break;
                __nanosleep(16);
            }
        }
        __syncthreads();
        __threadfence();
    }
}

// ---------------- final: logits, softmax, argmax ----------------
__global__ void k_final(const float* __restrict__ Wl, const float* __restrict__ bl,
                        float* __restrict__ out, int out_size)
{
    int p    = blockIdx.x*(blockDim.x>>5) + (threadIdx.x>>5);
    int lane = threadIdx.x & 31;
    if (p >= MR) return;

    const float* hf = g_hs[0] + (size_t)p*HH;
    const float* hb = g_hs[1] + (size_t)p*HH;

    float lg[NNER];
    #pragma unroll
    for (int n=0;n<NNER;n++) lg[n]=0.f;

    for (int k=lane; k<HH; k+=32){
        float hv  = hf[k];
        float hv2 = hb[k];
        #pragma unroll
        for (int n=0;n<NNER;n++){
            lg[n] += Wl[n*2*HH + k]*hv + Wl[n*2*HH + HH + k]*hv2;
        }
    }
    #pragma unroll
    for (int n=0;n<NNER;n++){
        #pragma unroll
        for (int o=16;o;o>>=1) lg[n] += __shfl_xor_sync(0xffffffffu, lg[n], o);
    }
    if (lane==0){
        float mx = -1e30f;
        #pragma unroll
        for (int n=0;n<NNER;n++){ lg[n] += bl[n]; mx = fmaxf(mx, lg[n]); }
        float e[NNER], sum=0.f;
        #pragma unroll
        for (int n=0;n<NNER;n++){ e[n] = expf(lg[n]-mx); sum += e[n]; }
        float inv = 1.0f/sum;
        int best = 0; float bv = lg[0];
        #pragma unroll
        for (int n=1;n<NNER;n++){ if (lg[n] > bv){ bv = lg[n]; best = n; } }
        #pragma unroll
        for (int n=0;n<NNER;n++) out[p*NNER + n] = e[n]*inv;
        if (out_size >= MR*NNER + MR) out[MR*NNER + p] = (float)best;
    }
}

// ---------------- launch ----------------
extern "C" void kernel_launch(void* const* d_in, const int* in_sizes, int n_in,
                              void* d_out, int out_size)
{
    const float* bert = (const float*)d_in[0];
    const int*   wid  = (const int*)  d_in[1];
    const float* Wihf = (const float*)d_in[2];
    const float* Whhf = (const float*)d_in[3];
    const float* bf   = (const float*)d_in[4];
    const float* Wihb = (const float*)d_in[5];
    const float* Whhb = (const float*)d_in[6];
    const float* bbv  = (const float*)d_in[7];
    const float* Wlin = (const float*)d_in[8];
    const float* blin = (const float*)d_in[9];

    static int smem_set = 0;
    const int pers_smem = (HH*CPB)*4 + NW*256*8 + (8*GWSZ)*4;  // 147456+32768+51200 = 231424 B
    if (!smem_set){
        cudaFuncSetAttribute(k_lstm_pers, cudaFuncAttributeMaxDynamicSharedMemorySize, pers_smem);
        smem_set = 1;
    }

    k_init<<<128, 256>>>();
    k_find<<<(BB*TT + 255)/256, 256>>>(wid);
    k_gather<<<MR, 192>>>(bert);
    k_gemm_xg<<<dim3(G4/128, MPAD/128, 2), 256>>>(Wihf, Wihb, bf, bbv);
    k_lstm_pers<<<NBLK, 512, pers_smem>>>(Whhf, Whhb);
    k_final<<<(MR + 3)/4, 128>>>(Wlin, blin, (float*)d_out, out_size);
}

// round 15
// speedup vs baseline: 1.0809x; 1.0809x over previous
#include <cuda_runtime.h>
#include <math.h>

#define BB 32
#define TT 512
#define DD 768
#define WW 255
#define HH 768
#define G4 3072           // 4*H
#define MR (BB*WW)        // 8160
#define MPAD 8192
#define NNER 9

// persistent LSTM kernel config
#define UPB 12            // hidden units per block
#define CPB 48            // gate columns per block (4*UPB)
#define NBD 64            // blocks per direction
#define NBLK (2*NBD)      // 128 total
#define NW 16             // warps per block
#define KPW 48            // k rows per warp (HH/16)
#define SC  8             // k rows per sub-chunk
#define NSC (KPW/SC)      // 6 sub-chunks
#define RP  40            // packed row pitch in ull (4 groups x 10; banks 0/20/8/28)
#define HBW (2*SC*RP)     // per-warp hb ull count (640)
#define GPITCH 50         // gred row pitch
#define GWSZ (BB*GPITCH)  // per-slot gred region (1600 floats)

// ---------------- scratch ----------------
__device__ int   g_fidx[MR];
__device__ float g_pooled[MPAD*DD];
__device__ float g_xg[2][(size_t)MPAD*G4];
__device__ float g_hstate[2][2][HH][BB];   // [buf][dir][k][m]
__device__ float g_hs[2][(size_t)MR*HH];
__device__ int   g_flag[2][NBD];           // per-block step counters

typedef unsigned long long ull;
struct __align__(16) ull2 { ull x, y; };

__device__ __forceinline__ void ffma2(ull &c, ull a, ull b){
    asm("fma.rn.f32x2 %0, %1, %2, %0;" : "+l"(c) : "l"(a), "l"(b));
}
__device__ __forceinline__ ull add2(ull a, ull b){
    ull r; asm("add.rn.f32x2 %0, %1, %2;" : "=l"(r) : "l"(a), "l"(b)); return r;
}
__device__ __forceinline__ ull splat2(float x){
    ull r; asm("mov.b64 %0, {%1, %1};" : "=l"(r) : "f"(x)); return r;
}
__device__ __forceinline__ float2 unpack2(ull v){
    float2 f; asm("mov.b64 {%0, %1}, %2;" : "=f"(f.x), "=f"(f.y) : "l"(v)); return f;
}
__device__ __forceinline__ float sigmoidf_(float x){ return 1.0f/(1.0f + expf(-x)); }
// volatile poll load — cannot be hoisted out of the spin loop
__device__ __forceinline__ int ld_poll(const int* p){
    int v; asm volatile("ld.global.cg.b32 %0, [%1];" : "=r"(v) : "l"(p) : "memory");
    return v;
}
// pack a float4 into 4 duplicated (h,h) ull pairs (2x STS.128)
__device__ __forceinline__ void pack_store(ull* dst, float4 v){
    ull2 a, b;
    a.x = splat2(v.x); a.y = splat2(v.y);
    b.x = splat2(v.z); b.y = splat2(v.w);
    ((ull2*)dst)[0] = a;
    ((ull2*)dst)[1] = b;
}

// ---------------- init ----------------
__global__ void k_init(){
    int i  = blockIdx.x*blockDim.x + threadIdx.x;
    int nt = gridDim.x*blockDim.x;
    for (int j=i; j<MR; j+=nt) g_fidx[j] = 0x7fffffff;
    for (int j=i; j<2*HH*BB; j+=nt) (&g_hstate[0][0][0][0])[j] = 0.f;   // buf0, both dirs
    for (int j=i; j<2*NBD; j+=nt) (&g_flag[0][0])[j] = 0;
    for (int j=i; j<(MPAD-MR)*DD; j+=nt) g_pooled[(size_t)MR*DD + j] = 0.f;
}

// ---------------- first-subword index ----------------
__global__ void k_find(const int* __restrict__ wid){
    int i = blockIdx.x*blockDim.x + threadIdx.x;
    if (i < BB*TT){
        int w = wid[i];
        if (w >= 0 && w < WW) atomicMin(&g_fidx[(i/TT)*WW + w], i % TT);
    }
}

// ---------------- gather pooled rows ----------------
__global__ void k_gather(const float* __restrict__ bert){
    int p   = blockIdx.x;
    int idx = g_fidx[p];
    if (idx >= TT) idx = 0;
    int b = p / WW;
    const float4* src = (const float4*)(bert + ((size_t)b*TT + idx)*DD);
    float4*       dst = (float4*)(g_pooled + (size_t)p*DD);
    dst[threadIdx.x] = src[threadIdx.x];
}

// ---------------- input-gate GEMM (R11 version, double-buffered) ----------------
__global__ __launch_bounds__(256, 2) void k_gemm_xg(
    const float* __restrict__ Wf, const float* __restrict__ Wb,
    const float* __restrict__ bf, const float* __restrict__ bbv)
{
    const float* Wm   = blockIdx.z ? Wb  : Wf;
    const float* bias = blockIdx.z ? bbv : bf;
    float* C = g_xg[blockIdx.z];

    __shared__ float As[2][16][128];
    __shared__ float Bs[2][16][128];

    int tid = threadIdx.x;
    int m0 = blockIdx.y*128, n0 = blockIdx.x*128;
    int tm  = (tid>>4)*8;
    int tn2 = (tid&15)*2;

    ull acc[8][4];
    #pragma unroll
    for (int i=0;i<8;i++){ acc[i][0]=0ull; acc[i][1]=0ull; acc[i][2]=0ull; acc[i][3]=0ull; }

    int r   = tid>>1;
    int kqa = (tid&1)*8;
    const float* Ag = g_pooled + (size_t)(m0+r)*DD + kqa;
    const float* Bg = Wm       + (size_t)(n0+r)*DD + kqa;

    float4 a0 = *(const float4*)(Ag);
    float4 a1 = *(const float4*)(Ag + 4);
    float4 b0 = *(const float4*)(Bg);
    float4 b1 = *(const float4*)(Bg + 4);
    As[0][kqa+0][r]=a0.x; As[0][kqa+1][r]=a0.y; As[0][kqa+2][r]=a0.z; As[0][kqa+3][r]=a0.w;
    As[0][kqa+4][r]=a1.x; As[0][kqa+5][r]=a1.y; As[0][kqa+6][r]=a1.z; As[0][kqa+7][r]=a1.w;
    Bs[0][kqa+0][r]=b0.x; Bs[0][kqa+1][r]=b0.y; Bs[0][kqa+2][r]=b0.z; Bs[0][kqa+3][r]=b0.w;
    Bs[0][kqa+4][r]=b1.x; Bs[0][kqa+5][r]=b1.y; Bs[0][kqa+6][r]=b1.z; Bs[0][kqa+7][r]=b1.w;
    __syncthreads();

    for (int kt=0; kt<48; kt++){
        int cur = kt & 1;
        if (kt < 47){
            int ko = (kt+1)*16;
            a0 = *(const float4*)(Ag + ko);
            a1 = *(const float4*)(Ag + ko + 4);
            b0 = *(const float4*)(Bg + ko);
            b1 = *(const float4*)(Bg + ko + 4);
        }
        #pragma unroll
        for (int kk=0; kk<16; kk++){
            float4 av0 = *(const float4*)&As[cur][kk][tm];
            float4 av1 = *(const float4*)&As[cur][kk][tm+4];
            ull bp0 = *(const ull*)&Bs[cur][kk][tn2];
            ull bp1 = *(const ull*)&Bs[cur][kk][tn2+32];
            ull bp2 = *(const ull*)&Bs[cur][kk][tn2+64];
            ull bp3 = *(const ull*)&Bs[cur][kk][tn2+96];
            float am[8] = {av0.x,av0.y,av0.z,av0.w,av1.x,av1.y,av1.z,av1.w};
            #pragma unroll
            for (int i=0;i<8;i++){
                ull as_ = splat2(am[i]);
                ffma2(acc[i][0], as_, bp0);
                ffma2(acc[i][1], as_, bp1);
                ffma2(acc[i][2], as_, bp2);
                ffma2(acc[i][3], as_, bp3);
            }
        }
        if (kt < 47){
            int nx = 1 - cur;
            As[nx][kqa+0][r]=a0.x; As[nx][kqa+1][r]=a0.y; As[nx][kqa+2][r]=a0.z; As[nx][kqa+3][r]=a0.w;
            As[nx][kqa+4][r]=a1.x; As[nx][kqa+5][r]=a1.y; As[nx][kqa+6][r]=a1.z; As[nx][kqa+7][r]=a1.w;
            Bs[nx][kqa+0][r]=b0.x; Bs[nx][kqa+1][r]=b0.y; Bs[nx][kqa+2][r]=b0.z; Bs[nx][kqa+3][r]=b0.w;
            Bs[nx][kqa+4][r]=b1.x; Bs[nx][kqa+5][r]=b1.y; Bs[nx][kqa+6][r]=b1.z; Bs[nx][kqa+7][r]=b1.w;
            __syncthreads();
        }
    }

    #pragma unroll
    for (int i=0;i<8;i++){
        float* crow = C + (size_t)(m0+tm+i)*G4 + n0;
        #pragma unroll
        for (int j=0;j<4;j++){
            float2 v = unpack2(acc[i][j]);
            v.x += bias[n0+tn2+32*j];
            v.y += bias[n0+tn2+32*j+1];
            *(float2*)(crow + tn2 + 32*j) = v;
        }
    }
}

// ---------------- persistent bidirectional LSTM ----------------
// 128 blocks x 512 threads (16 warps, 4/SMSP), 1 block/SM via ~224KB smem.
// Warp w owns k rows [w*48,(w+1)*48), staged warp-privately in 8-row double-
// buffered sub-chunks as PRE-PACKED (h,h) ull pairs with 40-ull padded rows
// (group stride 10 ull -> mh-group banks {0,20,8,28}: conflict-free LDS.128;
// splats at staging, zero MOV in inner loop). hb memory is ALIASED with gred
// (phase-disjoint; extra __syncthreads between GEMM and partial-dump).
__global__ __launch_bounds__(512, 1) void k_lstm_pers(
    const float* __restrict__ Whf, const float* __restrict__ Whb)
{
    extern __shared__ float sm[];
    float* ws   = sm;                              // [768][48]        147456 B
    ull*   hb   = (ull*)(sm + HH*CPB);             // 16 x 640 ull      81920 B
    float* gred = sm + HH*CPB;                     // ALIASES hb        51200 B used

    int tid = threadIdx.x;
    int bid = blockIdx.x;
    int d    = bid >> 6;
    int bid6 = bid & 63;
    int u0   = bid6 * UPB;
    const float* Wm = d ? Whb : Whf;
    int* flagd = g_flag[d];

    // stage weights: ws[k][c], c = g*UPB+uu
    for (int idx = tid; idx < CPB*(HH/4); idx += 512){
        int c  = idx / (HH/4);
        int kq = (idx % (HH/4)) * 4;
        int g = c / UPB, uu = c % UPB;
        float4 w = *(const float4*)(Wm + (size_t)(g*HH + u0 + uu)*HH + kq);
        ws[(kq+0)*CPB + c] = w.x;
        ws[(kq+1)*CPB + c] = w.y;
        ws[(kq+2)*CPB + c] = w.z;
        ws[(kq+3)*CPB + c] = w.w;
    }
    __syncthreads();

    int warp  = tid >> 5;
    int lane  = tid & 31;
    int mh    = lane >> 3;
    int cBase = (lane & 7) * 6;

    ull* hbw = hb + warp*HBW;                 // 2 bufs x 8 rows x 40 ull
    int  kwq4 = warp*KPW*8;                   // warp k-base in float4 units
    // staging: lane handles float4 idx = lane and lane+32 of each sub-chunk
    int  sr0 = lane >> 3, sq0 = lane & 7;     // idx = lane      -> row sr0
    ull* sd0 = hbw + sr0*RP + (sq0>>1)*10 + (sq0&1)*4;
    ull* sd1 = hbw + (sr0+4)*RP + (sq0>>1)*10 + (sq0&1)*4;   // idx = lane+32 -> row sr0+4

    const float* xg_d = g_xg[d];
    int uu1 = tid >> 5, mm1 = tid & 31;       // cell pair (tid<384)
    float c1 = 0.f;

    for (int s = 0; s < WW; s++){
        int t = d ? (WW-1-s) : s;
        const float4* hs4 = (const float4*)(&g_hstate[s&1][d][0][0]) + kwq4;
        float*        hdst = &g_hstate[(s+1)&1][d][0][0];

        // xg prefetch for cell phase
        float x1[4];
        if (tid < 384){
            const float* xb = xg_d + (size_t)(mm1*WW + t)*G4 + u0 + uu1;
            x1[0]=xb[0]; x1[1]=xb[HH]; x1[2]=xb[2*HH]; x1[3]=xb[3*HH];
        }

        // stage sub-chunk 0 (warp-private; L1 bypass: h written by remote SMs)
        float4 p0 = __ldcg(hs4 + lane);
        float4 p1 = __ldcg(hs4 + lane + 32);
        pack_store(sd0, p0);
        pack_store(sd1, p1);
        __syncwarp();

        ull acc[8][3];
        #pragma unroll
        for (int mi=0;mi<8;mi++){ acc[mi][0]=0ull; acc[mi][1]=0ull; acc[mi][2]=0ull; }

        for (int sc=0; sc<NSC; sc++){
            int cur = sc & 1;
            if (sc < NSC-1){
                p0 = __ldcg(hs4 + (sc+1)*64 + lane);
                p1 = __ldcg(hs4 + (sc+1)*64 + lane + 32);
            }
            const ull*   hc = hbw + cur*(SC*RP) + mh*10;
            const float* wc = ws + (warp*KPW + sc*SC)*CPB + cBase;
            #pragma unroll
            for (int r=0; r<SC; r++){
                const ull* hp = hc + r*RP;
                ull2 h01 = *(const ull2*)(hp);
                ull2 h23 = *(const ull2*)(hp + 2);
                ull2 h45 = *(const ull2*)(hp + 4);
                ull2 h67 = *(const ull2*)(hp + 6);
                ull w0 = *(const ull*)(wc + r*CPB);
                ull w1 = *(const ull*)(wc + r*CPB + 2);
                ull w2 = *(const ull*)(wc + r*CPB + 4);
                ffma2(acc[0][0],h01.x,w0); ffma2(acc[0][1],h01.x,w1); ffma2(acc[0][2],h01.x,w2);
                ffma2(acc[1][0],h01.y,w0); ffma2(acc[1][1],h01.y,w1); ffma2(acc[1][2],h01.y,w2);
                ffma2(acc[2][0],h23.x,w0); ffma2(acc[2][1],h23.x,w1); ffma2(acc[2][2],h23.x,w2);
                ffma2(acc[3][0],h23.y,w0); ffma2(acc[3][1],h23.y,w1); ffma2(acc[3][2],h23.y,w2);
                ffma2(acc[4][0],h45.x,w0); ffma2(acc[4][1],h45.x,w1); ffma2(acc[4][2],h45.x,w2);
                ffma2(acc[5][0],h45.y,w0); ffma2(acc[5][1],h45.y,w1); ffma2(acc[5][2],h45.y,w2);
                ffma2(acc[6][0],h67.x,w0); ffma2(acc[6][1],h67.x,w1); ffma2(acc[6][2],h67.x,w2);
                ffma2(acc[7][0],h67.y,w0); ffma2(acc[7][1],h67.y,w1); ffma2(acc[7][2],h67.y,w2);
            }
            if (sc < NSC-1){
                int nx = 1 - cur;
                pack_store(hbw + nx*(SC*RP) + sr0*RP + (sq0>>1)*10 + (sq0&1)*4, p0);
                pack_store(hbw + nx*(SC*RP) + (sr0+4)*RP + (sq0>>1)*10 + (sq0&1)*4, p1);
            }
            __syncwarp();
        }

        // ALL warps must finish GEMM (hb reads) before gred (aliased) is written
        __syncthreads();

        // reduction phase 1: warps 8-15 dump partials to gred[warp-8]
        if (warp >= 8){
            float* gr = gred + (warp-8)*GWSZ + mh*8*GPITCH + cBase;
            #pragma unroll
            for (int mi=0;mi<8;mi++){
                float* row = gr + mi*GPITCH;
                *(float2*)(row    ) = unpack2(acc[mi][0]);
                *(float2*)(row + 2) = unpack2(acc[mi][1]);
                *(float2*)(row + 4) = unpack2(acc[mi][2]);
            }
        }
        __syncthreads();

        // phase 2: warps 0-7 fold partner (warp+8) partials, dump 2-way sums
        if (warp < 8){
            float* gr = gred + warp*GWSZ + mh*8*GPITCH + cBase;
            #pragma unroll
            for (int mi=0;mi<8;mi++){
                float* row = gr + mi*GPITCH;
                ull v0 = add2(acc[mi][0], *(const ull*)(row    ));
                ull v1 = add2(acc[mi][1], *(const ull*)(row + 2));
                ull v2 = add2(acc[mi][2], *(const ull*)(row + 4));
                *(float2*)(row    ) = unpack2(v0);
                *(float2*)(row + 2) = unpack2(v1);
                *(float2*)(row + 4) = unpack2(v2);
            }
        }
        __syncthreads();

        // LSTM cell: sum 8 slots + xg (tid<384: one (u,m) pair each)
        if (tid < 384){
            int base = mm1*GPITCH + uu1;
            float gi=x1[0], gf=x1[1], gg=x1[2], go=x1[3];
            #pragma unroll
            for (int w=0; w<8; w++){
                const float* g = gred + w*GWSZ + base;
                gi += g[0]; gf += g[UPB]; gg += g[2*UPB]; go += g[3*UPB];
            }
            float cn = sigmoidf_(gf)*c1 + sigmoidf_(gi)*tanhf(gg);
            float h  = sigmoidf_(go)*tanhf(cn);
            c1 = cn;
            hdst[(u0+uu1)*BB + mm1] = h;
            g_hs[d][(size_t)(mm1*WW + t)*HH + u0 + uu1] = h;
        }

        // inter-block barrier: per-block flag + poll-all (volatile loads)
        __threadfence();
        __syncthreads();
        if (tid == 0) atomicExch(&flagd[bid6], s+1);
        if (tid < 32){
            int tgt = s + 1;
            while (true){
                int a = ld_poll(&flagd[tid]);
                int b = ld_poll(&flagd[tid+32]);
                if (__all_sync(0xffffffffu, (a >= tgt) && (b >= tgt))) break;
                __nanosleep(16);
            }
        }
        __syncthreads();
        __threadfence();
    }
}

// ---------------- final: logits, softmax, argmax ----------------
__global__ void k_final(const float* __restrict__ Wl, const float* __restrict__ bl,
                        float* __restrict__ out, int out_size)
{
    int p    = blockIdx.x*(blockDim.x>>5) + (threadIdx.x>>5);
    int lane = threadIdx.x & 31;
    if (p >= MR) return;

    const float* hf = g_hs[0] + (size_t)p*HH;
    const float* hb = g_hs[1] + (size_t)p*HH;

    float lg[NNER];
    #pragma unroll
    for (int n=0;n<NNER;n++) lg[n]=0.f;

    for (int k=lane; k<HH; k+=32){
        float hv  = hf[k];
        float hv2 = hb[k];
        #pragma unroll
        for (int n=0;n<NNER;n++){
            lg[n] += Wl[n*2*HH + k]*hv + Wl[n*2*HH + HH + k]*hv2;
        }
    }
    #pragma unroll
    for (int n=0;n<NNER;n++){
        #pragma unroll
        for (int o=16;o;o>>=1) lg[n] += __shfl_xor_sync(0xffffffffu, lg[n], o);
    }
    if (lane==0){
        float mx = -1e30f;
        #pragma unroll
        for (int n=0;n<NNER;n++){ lg[n] += bl[n]; mx = fmaxf(mx, lg[n]); }
        float e[NNER], sum=0.f;
        #pragma unroll
        for (int n=0;n<NNER;n++){ e[n] = expf(lg[n]-mx); sum += e[n]; }
        float inv = 1.0f/sum;
        int best = 0; float bv = lg[0];
        #pragma unroll
        for (int n=1;n<NNER;n++){ if (lg[n] > bv){ bv = lg[n]; best = n; } }
        #pragma unroll
        for (int n=0;n<NNER;n++) out[p*NNER + n] = e[n]*inv;
        if (out_size >= MR*NNER + MR) out[MR*NNER + p] = (float)best;
    }
}

// ---------------- launch ----------------
extern "C" void kernel_launch(void* const* d_in, const int* in_sizes, int n_in,
                              void* d_out, int out_size)
{
    const float* bert = (const float*)d_in[0];
    const int*   wid  = (const int*)  d_in[1];
    const float* Wihf = (const float*)d_in[2];
    const float* Whhf = (const float*)d_in[3];
    const float* bf   = (const float*)d_in[4];
    const float* Wihb = (const float*)d_in[5];
    const float* Whhb = (const float*)d_in[6];
    const float* bbv  = (const float*)d_in[7];
    const float* Wlin = (const float*)d_in[8];
    const float* blin = (const float*)d_in[9];

    static int smem_set = 0;
    const int pers_smem = (HH*CPB)*4 + NW*HBW*8;   // 147456 + 81920 = 229376 B
    if (!smem_set){
        cudaFuncSetAttribute(k_lstm_pers, cudaFuncAttributeMaxDynamicSharedMemorySize, pers_smem);
        smem_set = 1;
    }

    k_init<<<128, 256>>>();
    k_find<<<(BB*TT + 255)/256, 256>>>(wid);
    k_gather<<<MR, 192>>>(bert);
    k_gemm_xg<<<dim3(G4/128, MPAD/128, 2), 256>>>(Wihf, Wihb, bf, bbv);
    k_lstm_pers<<<NBLK, 512, pers_smem>>>(Whhf, Whhb);
    k_final<<<(MR + 3)/4, 128>>>(Wlin, blin, (float*)d_out, out_size);
}

// round 16
// speedup vs baseline: 1.2639x; 1.1693x over previous
#include <cuda_runtime.h>
#include <math.h>

#define BB 32
#define TT 512
#define DD 768
#define WW 255
#define HH 768
#define G4 3072           // 4*H
#define MR (BB*WW)        // 8160
#define MPAD 8192
#define NNER 9

// persistent LSTM kernel config
#define UPB 12            // hidden units per block
#define CPB 48            // gate columns per block (4*UPB)
#define NBD 64            // blocks per direction
#define NBLK (2*NBD)      // 128 total
#define NW 16             // warps per block
#define KPW 48            // k rows per warp (HH/16)
#define SC  8             // k rows per sub-chunk
#define NSC (KPW/SC)      // 6 sub-chunks
#define GPITCH 50         // gred row pitch
#define GWSZ (BB*GPITCH)  // per-slot gred region (1600 floats)

// ---------------- scratch ----------------
__device__ int   g_fidx[MR];
__device__ float g_pooled[MPAD*DD];
__device__ float g_xg[2][(size_t)MPAD*G4];
__device__ float g_hstate[2][2][HH][BB];   // [buf][dir][k][m]
__device__ float g_hs[2][(size_t)MR*HH];
__device__ int   g_flag[2][NBD];           // per-block step counters

typedef unsigned long long ull;

__device__ __forceinline__ void ffma2(ull &c, ull a, ull b){
    asm("fma.rn.f32x2 %0, %1, %2, %0;" : "+l"(c) : "l"(a), "l"(b));
}
__device__ __forceinline__ ull add2(ull a, ull b){
    ull r; asm("add.rn.f32x2 %0, %1, %2;" : "=l"(r) : "l"(a), "l"(b)); return r;
}
__device__ __forceinline__ ull splat2(float x){
    ull r; asm("mov.b64 %0, {%1, %1};" : "=l"(r) : "f"(x)); return r;
}
__device__ __forceinline__ float2 unpack2(ull v){
    float2 f; asm("mov.b64 {%0, %1}, %2;" : "=f"(f.x), "=f"(f.y) : "l"(v)); return f;
}
__device__ __forceinline__ float sigmoidf_(float x){ return 1.0f/(1.0f + expf(-x)); }
// volatile poll load — cannot be hoisted out of the spin loop
__device__ __forceinline__ int ld_poll(const int* p){
    int v; asm volatile("ld.global.cg.b32 %0, [%1];" : "=r"(v) : "l"(p) : "memory");
    return v;
}

// ---------------- init ----------------
__global__ void k_init(){
    int i  = blockIdx.x*blockDim.x + threadIdx.x;
    int nt = gridDim.x*blockDim.x;
    for (int j=i; j<MR; j+=nt) g_fidx[j] = 0x7fffffff;
    for (int j=i; j<2*HH*BB; j+=nt) (&g_hstate[0][0][0][0])[j] = 0.f;   // buf0, both dirs
    for (int j=i; j<2*NBD; j+=nt) (&g_flag[0][0])[j] = 0;
    for (int j=i; j<(MPAD-MR)*DD; j+=nt) g_pooled[(size_t)MR*DD + j] = 0.f;
}

// ---------------- first-subword index ----------------
__global__ void k_find(const int* __restrict__ wid){
    int i = blockIdx.x*blockDim.x + threadIdx.x;
    if (i < BB*TT){
        int w = wid[i];
        if (w >= 0 && w < WW) atomicMin(&g_fidx[(i/TT)*WW + w], i % TT);
    }
}

// ---------------- gather pooled rows ----------------
__global__ void k_gather(const float* __restrict__ bert){
    int p   = blockIdx.x;
    int idx = g_fidx[p];
    if (idx >= TT) idx = 0;
    int b = p / WW;
    const float4* src = (const float4*)(bert + ((size_t)b*TT + idx)*DD);
    float4*       dst = (float4*)(g_pooled + (size_t)p*DD);
    dst[threadIdx.x] = src[threadIdx.x];
}

// ---------------- input-gate GEMM (R11 version, double-buffered) ----------------
__global__ __launch_bounds__(256, 2) void k_gemm_xg(
    const float* __restrict__ Wf, const float* __restrict__ Wb,
    const float* __restrict__ bf, const float* __restrict__ bbv)
{
    const float* Wm   = blockIdx.z ? Wb  : Wf;
    const float* bias = blockIdx.z ? bbv : bf;
    float* C = g_xg[blockIdx.z];

    __shared__ float As[2][16][128];
    __shared__ float Bs[2][16][128];

    int tid = threadIdx.x;
    int m0 = blockIdx.y*128, n0 = blockIdx.x*128;
    int tm  = (tid>>4)*8;
    int tn2 = (tid&15)*2;

    ull acc[8][4];
    #pragma unroll
    for (int i=0;i<8;i++){ acc[i][0]=0ull; acc[i][1]=0ull; acc[i][2]=0ull; acc[i][3]=0ull; }

    int r   = tid>>1;
    int kqa = (tid&1)*8;
    const float* Ag = g_pooled + (size_t)(m0+r)*DD + kqa;
    const float* Bg = Wm       + (size_t)(n0+r)*DD + kqa;

    float4 a0 = *(const float4*)(Ag);
    float4 a1 = *(const float4*)(Ag + 4);
    float4 b0 = *(const float4*)(Bg);
    float4 b1 = *(const float4*)(Bg + 4);
    As[0][kqa+0][r]=a0.x; As[0][kqa+1][r]=a0.y; As[0][kqa+2][r]=a0.z; As[0][kqa+3][r]=a0.w;
    As[0][kqa+4][r]=a1.x; As[0][kqa+5][r]=a1.y; As[0][kqa+6][r]=a1.z; As[0][kqa+7][r]=a1.w;
    Bs[0][kqa+0][r]=b0.x; Bs[0][kqa+1][r]=b0.y; Bs[0][kqa+2][r]=b0.z; Bs[0][kqa+3][r]=b0.w;
    Bs[0][kqa+4][r]=b1.x; Bs[0][kqa+5][r]=b1.y; Bs[0][kqa+6][r]=b1.z; Bs[0][kqa+7][r]=b1.w;
    __syncthreads();

    for (int kt=0; kt<48; kt++){
        int cur = kt & 1;
        if (kt < 47){
            int ko = (kt+1)*16;
            a0 = *(const float4*)(Ag + ko);
            a1 = *(const float4*)(Ag + ko + 4);
            b0 = *(const float4*)(Bg + ko);
            b1 = *(const float4*)(Bg + ko + 4);
        }
        #pragma unroll
        for (int kk=0; kk<16; kk++){
            float4 av0 = *(const float4*)&As[cur][kk][tm];
            float4 av1 = *(const float4*)&As[cur][kk][tm+4];
            ull bp0 = *(const ull*)&Bs[cur][kk][tn2];
            ull bp1 = *(const ull*)&Bs[cur][kk][tn2+32];
            ull bp2 = *(const ull*)&Bs[cur][kk][tn2+64];
            ull bp3 = *(const ull*)&Bs[cur][kk][tn2+96];
            float am[8] = {av0.x,av0.y,av0.z,av0.w,av1.x,av1.y,av1.z,av1.w};
            #pragma unroll
            for (int i=0;i<8;i++){
                ull as_ = splat2(am[i]);
                ffma2(acc[i][0], as_, bp0);
                ffma2(acc[i][1], as_, bp1);
                ffma2(acc[i][2], as_, bp2);
                ffma2(acc[i][3], as_, bp3);
            }
        }
        if (kt < 47){
            int nx = 1 - cur;
            As[nx][kqa+0][r]=a0.x; As[nx][kqa+1][r]=a0.y; As[nx][kqa+2][r]=a0.z; As[nx][kqa+3][r]=a0.w;
            As[nx][kqa+4][r]=a1.x; As[nx][kqa+5][r]=a1.y; As[nx][kqa+6][r]=a1.z; As[nx][kqa+7][r]=a1.w;
            Bs[nx][kqa+0][r]=b0.x; Bs[nx][kqa+1][r]=b0.y; Bs[nx][kqa+2][r]=b0.z; Bs[nx][kqa+3][r]=b0.w;
            Bs[nx][kqa+4][r]=b1.x; Bs[nx][kqa+5][r]=b1.y; Bs[nx][kqa+6][r]=b1.z; Bs[nx][kqa+7][r]=b1.w;
            __syncthreads();
        }
    }

    #pragma unroll
    for (int i=0;i<8;i++){
        float* crow = C + (size_t)(m0+tm+i)*G4 + n0;
        #pragma unroll
        for (int j=0;j<4;j++){
            float2 v = unpack2(acc[i][j]);
            v.x += bias[n0+tn2+32*j];
            v.y += bias[n0+tn2+32*j+1];
            *(float2*)(crow + tn2 + 32*j) = v;
        }
    }
}

// ---------------- persistent bidirectional LSTM ----------------
// R11 structure (16 warps, warp-private unpacked staging) with a streamlined
// end-of-step tail: pairwise named barriers for the reduction handoff, no
// reader-side threadfence, g_hs history stores moved into the poll shadow.
__global__ __launch_bounds__(512, 1) void k_lstm_pers(
    const float* __restrict__ Whf, const float* __restrict__ Whb)
{
    extern __shared__ float sm[];
    float* ws   = sm;                              // [768][48]     147456 B
    float* hb   = sm + HH*CPB;                     // 16 warps x 512 floats = 32768 B
    float* gred = hb + NW*512;                     // [8][32][50]    51200 B

    int tid = threadIdx.x;
    int bid = blockIdx.x;
    int d    = bid >> 6;
    int bid6 = bid & 63;
    int u0   = bid6 * UPB;
    const float* Wm = d ? Whb : Whf;
    int* flagd = g_flag[d];

    // stage weights: ws[k][c], c = g*UPB+uu
    for (int idx = tid; idx < CPB*(HH/4); idx += 512){
        int c  = idx / (HH/4);
        int kq = (idx % (HH/4)) * 4;
        int g = c / UPB, uu = c % UPB;
        float4 w = *(const float4*)(Wm + (size_t)(g*HH + u0 + uu)*HH + kq);
        ws[(kq+0)*CPB + c] = w.x;
        ws[(kq+1)*CPB + c] = w.y;
        ws[(kq+2)*CPB + c] = w.z;
        ws[(kq+3)*CPB + c] = w.w;
    }
    __syncthreads();

    int warp  = tid >> 5;
    int lane  = tid & 31;
    int mh    = lane >> 3;
    int mBase = mh * 8;
    int cBase = (lane & 7) * 6;

    float* hbw = hb + warp*512;               // 2 bufs x 8 rows x 32 floats
    int    kwq = warp*KPW*8;                  // warp k-base in float4 units

    const float* xg_d = g_xg[d];
    int uu1 = tid >> 5, mm1 = tid & 31;       // cell pair (tid<384)
    float c1 = 0.f;
    int pairbar = (warp & 7) + 1;             // named barrier id for (w, w+8)

    for (int s = 0; s < WW; s++){
        int t = d ? (WW-1-s) : s;
        const float4* hs4 = (const float4*)(&g_hstate[s&1][d][0][0]) + kwq;
        float*        hdst = &g_hstate[(s+1)&1][d][0][0];

        // issue h staging loads FIRST (earliest L2 issue after the barrier)
        float4 p0 = __ldcg(hs4 + lane);
        float4 p1 = __ldcg(hs4 + lane + 32);

        // xg prefetch for cell phase (independent, issues under the h loads)
        float x1[4];
        if (tid < 384){
            const float* xb = xg_d + (size_t)(mm1*WW + t)*G4 + u0 + uu1;
            x1[0]=xb[0]; x1[1]=xb[HH]; x1[2]=xb[2*HH]; x1[3]=xb[3*HH];
        }

        ((float4*)hbw)[lane]      = p0;
        ((float4*)hbw)[lane + 32] = p1;
        __syncwarp();

        ull acc[8][3];
        #pragma unroll
        for (int mi=0;mi<8;mi++){ acc[mi][0]=0ull; acc[mi][1]=0ull; acc[mi][2]=0ull; }

        for (int sc=0; sc<NSC; sc++){
            int cur = sc & 1;
            if (sc < NSC-1){
                p0 = __ldcg(hs4 + (sc+1)*64 + lane);
                p1 = __ldcg(hs4 + (sc+1)*64 + lane + 32);
            }
            const float* hc = hbw + cur*256 + mBase;
            const float* wc = ws + (warp*KPW + sc*SC)*CPB + cBase;
            #pragma unroll
            for (int r=0; r<SC; r++){
                float4 h0 = *(const float4*)(hc + r*32);
                float4 h1 = *(const float4*)(hc + r*32 + 4);
                ull w0 = *(const ull*)(wc + r*CPB);
                ull w1 = *(const ull*)(wc + r*CPB + 2);
                ull w2 = *(const ull*)(wc + r*CPB + 4);
                ull a;
                a = splat2(h0.x); ffma2(acc[0][0],a,w0); ffma2(acc[0][1],a,w1); ffma2(acc[0][2],a,w2);
                a = splat2(h0.y); ffma2(acc[1][0],a,w0); ffma2(acc[1][1],a,w1); ffma2(acc[1][2],a,w2);
                a = splat2(h0.z); ffma2(acc[2][0],a,w0); ffma2(acc[2][1],a,w1); ffma2(acc[2][2],a,w2);
                a = splat2(h0.w); ffma2(acc[3][0],a,w0); ffma2(acc[3][1],a,w1); ffma2(acc[3][2],a,w2);
                a = splat2(h1.x); ffma2(acc[4][0],a,w0); ffma2(acc[4][1],a,w1); ffma2(acc[4][2],a,w2);
                a = splat2(h1.y); ffma2(acc[5][0],a,w0); ffma2(acc[5][1],a,w1); ffma2(acc[5][2],a,w2);
                a = splat2(h1.z); ffma2(acc[6][0],a,w0); ffma2(acc[6][1],a,w1); ffma2(acc[6][2],a,w2);
                a = splat2(h1.w); ffma2(acc[7][0],a,w0); ffma2(acc[7][1],a,w1); ffma2(acc[7][2],a,w2);
            }
            if (sc < NSC-1){
                int nx = 1 - cur;
                ((float4*)(hbw + nx*256))[lane]      = p0;
                ((float4*)(hbw + nx*256))[lane + 32] = p1;
            }
            __syncwarp();
        }

        // reduction phase 1: warps 8-15 dump partials to gred[warp-8]
        if (warp >= 8){
            float* gr = gred + (warp-8)*GWSZ + mBase*GPITCH + cBase;
            #pragma unroll
            for (int mi=0;mi<8;mi++){
                float* row = gr + mi*GPITCH;
                *(float2*)(row    ) = unpack2(acc[mi][0]);
                *(float2*)(row + 2) = unpack2(acc[mi][1]);
                *(float2*)(row + 4) = unpack2(acc[mi][2]);
            }
        }
        // pairwise handoff: warp w <-> warp w+8 only (64-thread named barrier)
        asm volatile("bar.sync %0, 64;" :: "r"(pairbar) : "memory");

        // phase 2: warps 0-7 fold partner (warp+8) partials, dump 2-way sums
        if (warp < 8){
            float* gr = gred + warp*GWSZ + mBase*GPITCH + cBase;
            #pragma unroll
            for (int mi=0;mi<8;mi++){
                float* row = gr + mi*GPITCH;
                ull v0 = add2(acc[mi][0], *(const ull*)(row    ));
                ull v1 = add2(acc[mi][1], *(const ull*)(row + 2));
                ull v2 = add2(acc[mi][2], *(const ull*)(row + 4));
                *(float2*)(row    ) = unpack2(v0);
                *(float2*)(row + 2) = unpack2(v1);
                *(float2*)(row + 4) = unpack2(v2);
            }
        }
        __syncthreads();

        // LSTM cell: sum 8 slots + xg; store ONLY hdst here (critical path)
        float hval = 0.f;
        if (tid < 384){
            int base = mm1*GPITCH + uu1;
            float gi=x1[0], gf=x1[1], gg=x1[2], go=x1[3];
            #pragma unroll
            for (int w=0; w<8; w++){
                const float* g = gred + w*GWSZ + base;
                gi += g[0]; gf += g[UPB]; gg += g[2*UPB]; go += g[3*UPB];
            }
            float cn = sigmoidf_(gf)*c1 + sigmoidf_(gi)*tanhf(gg);
            hval = sigmoidf_(go)*tanhf(cn);
            c1 = cn;
            hdst[(u0+uu1)*BB + mm1] = hval;
        }

        // writer-side fence (orders hdst stores before the flag), then flag
        __threadfence();
        __syncthreads();
        if (tid == 0) atomicExch(&flagd[bid6], s+1);

        // g_hs history store in the poll shadow (not flag-covered; read only
        // by k_final after kernel completion)
        if (tid < 384)
            g_hs[d][(size_t)(mm1*WW + t)*HH + u0 + uu1] = hval;

        if (tid < 32){
            int tgt = s + 1;
            while (true){
                int a = ld_poll(&flagd[tid]);
                int b = ld_poll(&flagd[tid+32]);
                if (__all_sync(0xffffffffu, (a >= tgt) && (b >= tgt))) break;
                __nanosleep(16);
            }
        }
        __syncthreads();
        // no reader-side fence: h reads below use ld.cg (L2) issued after the
        // BAR; producer h stores are write-through to L2 and fenced before flag
    }
}

// ---------------- final: logits, softmax, argmax ----------------
__global__ void k_final(const float* __restrict__ Wl, const float* __restrict__ bl,
                        float* __restrict__ out, int out_size)
{
    int p    = blockIdx.x*(blockDim.x>>5) + (threadIdx.x>>5);
    int lane = threadIdx.x & 31;
    if (p >= MR) return;

    const float* hf = g_hs[0] + (size_t)p*HH;
    const float* hb = g_hs[1] + (size_t)p*HH;

    float lg[NNER];
    #pragma unroll
    for (int n=0;n<NNER;n++) lg[n]=0.f;

    for (int k=lane; k<HH; k+=32){
        float hv  = hf[k];
        float hv2 = hb[k];
        #pragma unroll
        for (int n=0;n<NNER;n++){
            lg[n] += Wl[n*2*HH + k]*hv + Wl[n*2*HH + HH + k]*hv2;
        }
    }
    #pragma unroll
    for (int n=0;n<NNER;n++){
        #pragma unroll
        for (int o=16;o;o>>=1) lg[n] += __shfl_xor_sync(0xffffffffu, lg[n], o);
    }
    if (lane==0){
        float mx = -1e30f;
        #pragma unroll
        for (int n=0;n<NNER;n++){ lg[n] += bl[n]; mx = fmaxf(mx, lg[n]); }
        float e[NNER], sum=0.f;
        #pragma unroll
        for (int n=0;n<NNER;n++){ e[n] = expf(lg[n]-mx); sum += e[n]; }
        float inv = 1.0f/sum;
        int best = 0; float bv = lg[0];
        #pragma unroll
        for (int n=1;n<NNER;n++){ if (lg[n] > bv){ bv = lg[n]; best = n; } }
        #pragma unroll
        for (int n=0;n<NNER;n++) out[p*NNER + n] = e[n]*inv;
        if (out_size >= MR*NNER + MR) out[MR*NNER + p] = (float)best;
    }
}

// ---------------- launch ----------------
extern "C" void kernel_launch(void* const* d_in, const int* in_sizes, int n_in,
                              void* d_out, int out_size)
{
    const float* bert = (const float*)d_in[0];
    const int*   wid  = (const int*)  d_in[1];
    const float* Wihf = (const float*)d_in[2];
    const float* Whhf = (const float*)d_in[3];
    const float* bf   = (const float*)d_in[4];
    const float* Wihb = (const float*)d_in[5];
    const float* Whhb = (const float*)d_in[6];
    const float* bbv  = (const float*)d_in[7];
    const float* Wlin = (const float*)d_in[8];
    const float* blin = (const float*)d_in[9];

    static int smem_set = 0;
    const int pers_smem = (HH*CPB)*4 + NW*512*4 + (8*GWSZ)*4;  // 231424 B
    if (!smem_set){
        cudaFuncSetAttribute(k_lstm_pers, cudaFuncAttributeMaxDynamicSharedMemorySize, pers_smem);
        smem_set = 1;
    }

    k_init<<<128, 256>>>();
    k_find<<<(BB*TT + 255)/256, 256>>>(wid);
    k_gather<<<MR, 192>>>(bert);
    k_gemm_xg<<<dim3(G4/128, MPAD/128, 2), 256>>>(Wihf, Wihb, bf, bbv);
    k_lstm_pers<<<NBLK, 512, pers_smem>>>(Whhf, Whhb);
    k_final<<<(MR + 3)/4, 128>>>(Wlin, blin, (float*)d_out, out_size);
}

// round 17
// speedup vs baseline: 1.3392x; 1.0596x over previous
#include <cuda_runtime.h>
#include <math.h>

#define BB 32
#define TT 512
#define DD 768
#define WW 255
#define HH 768
#define G4 3072           // 4*H
#define MR (BB*WW)        // 8160
#define MPAD 8192
#define NNER 9

// persistent LSTM kernel config
#define UPB 12            // hidden units per block
#define CPB 48            // gate columns per block (4*UPB)
#define NBD 64            // blocks per direction
#define NBLK (2*NBD)      // 128 total
#define NW 16             // warps per block
#define KPW 48            // k rows per warp (HH/16)
#define SC  8             // k rows per sub-chunk
#define NSC (KPW/SC)      // 6 sub-chunks
#define GPITCH 50         // gred row pitch
#define GWSZ (BB*GPITCH)  // per-slot gred region (1600 floats)

// ---------------- scratch ----------------
__device__ int   g_fidx[MR];
__device__ float g_pooled[MPAD*DD];
__device__ float g_xg[2][(size_t)MPAD*G4];
__device__ float g_hstate[2][2][HH][BB];   // [buf][dir][k][m]
__device__ float g_hs[2][(size_t)MR*HH];
__device__ int   g_flag[2][NBD];           // per-block step counters

typedef unsigned long long ull;

__device__ __forceinline__ void ffma2(ull &c, ull a, ull b){
    asm("fma.rn.f32x2 %0, %1, %2, %0;" : "+l"(c) : "l"(a), "l"(b));
}
__device__ __forceinline__ ull add2(ull a, ull b){
    ull r; asm("add.rn.f32x2 %0, %1, %2;" : "=l"(r) : "l"(a), "l"(b)); return r;
}
__device__ __forceinline__ ull splat2(float x){
    ull r; asm("mov.b64 %0, {%1, %1};" : "=l"(r) : "f"(x)); return r;
}
__device__ __forceinline__ float2 unpack2(ull v){
    float2 f; asm("mov.b64 {%0, %1}, %2;" : "=f"(f.x), "=f"(f.y) : "l"(v)); return f;
}
// fast sigmoid/tanh via EX2 (error ~1e-6; threshold is 1e-3)
__device__ __forceinline__ float fsig(float x){
    return __fdividef(1.0f, 1.0f + __expf(-x));
}
__device__ __forceinline__ float ftanh_(float x){
    return __fdividef(2.0f, 1.0f + __expf(-2.0f*x)) - 1.0f;
}
// volatile poll load — cannot be hoisted out of the spin loop
__device__ __forceinline__ int ld_poll(const int* p){
    int v; asm volatile("ld.global.cg.b32 %0, [%1];" : "=r"(v) : "l"(p) : "memory");
    return v;
}

// ---------------- init ----------------
__global__ void k_init(){
    int i  = blockIdx.x*blockDim.x + threadIdx.x;
    int nt = gridDim.x*blockDim.x;
    for (int j=i; j<MR; j+=nt) g_fidx[j] = 0x7fffffff;
    for (int j=i; j<2*HH*BB; j+=nt) (&g_hstate[0][0][0][0])[j] = 0.f;   // buf0, both dirs
    for (int j=i; j<2*NBD; j+=nt) (&g_flag[0][0])[j] = 0;
    for (int j=i; j<(MPAD-MR)*DD; j+=nt) g_pooled[(size_t)MR*DD + j] = 0.f;
}

// ---------------- first-subword index ----------------
__global__ void k_find(const int* __restrict__ wid){
    int i = blockIdx.x*blockDim.x + threadIdx.x;
    if (i < BB*TT){
        int w = wid[i];
        if (w >= 0 && w < WW) atomicMin(&g_fidx[(i/TT)*WW + w], i % TT);
    }
}

// ---------------- gather pooled rows ----------------
__global__ void k_gather(const float* __restrict__ bert){
    int p   = blockIdx.x;
    int idx = g_fidx[p];
    if (idx >= TT) idx = 0;
    int b = p / WW;
    const float4* src = (const float4*)(bert + ((size_t)b*TT + idx)*DD);
    float4*       dst = (float4*)(g_pooled + (size_t)p*DD);
    dst[threadIdx.x] = src[threadIdx.x];
}

// ---------------- input-gate GEMM (double-buffered) ----------------
__global__ __launch_bounds__(256, 2) void k_gemm_xg(
    const float* __restrict__ Wf, const float* __restrict__ Wb,
    const float* __restrict__ bf, const float* __restrict__ bbv)
{
    const float* Wm   = blockIdx.z ? Wb  : Wf;
    const float* bias = blockIdx.z ? bbv : bf;
    float* C = g_xg[blockIdx.z];

    __shared__ float As[2][16][128];
    __shared__ float Bs[2][16][128];

    int tid = threadIdx.x;
    int m0 = blockIdx.y*128, n0 = blockIdx.x*128;
    int tm  = (tid>>4)*8;
    int tn2 = (tid&15)*2;

    ull acc[8][4];
    #pragma unroll
    for (int i=0;i<8;i++){ acc[i][0]=0ull; acc[i][1]=0ull; acc[i][2]=0ull; acc[i][3]=0ull; }

    int r   = tid>>1;
    int kqa = (tid&1)*8;
    const float* Ag = g_pooled + (size_t)(m0+r)*DD + kqa;
    const float* Bg = Wm       + (size_t)(n0+r)*DD + kqa;

    float4 a0 = *(const float4*)(Ag);
    float4 a1 = *(const float4*)(Ag + 4);
    float4 b0 = *(const float4*)(Bg);
    float4 b1 = *(const float4*)(Bg + 4);
    As[0][kqa+0][r]=a0.x; As[0][kqa+1][r]=a0.y; As[0][kqa+2][r]=a0.z; As[0][kqa+3][r]=a0.w;
    As[0][kqa+4][r]=a1.x; As[0][kqa+5][r]=a1.y; As[0][kqa+6][r]=a1.z; As[0][kqa+7][r]=a1.w;
    Bs[0][kqa+0][r]=b0.x; Bs[0][kqa+1][r]=b0.y; Bs[0][kqa+2][r]=b0.z; Bs[0][kqa+3][r]=b0.w;
    Bs[0][kqa+4][r]=b1.x; Bs[0][kqa+5][r]=b1.y; Bs[0][kqa+6][r]=b1.z; Bs[0][kqa+7][r]=b1.w;
    __syncthreads();

    for (int kt=0; kt<48; kt++){
        int cur = kt & 1;
        if (kt < 47){
            int ko = (kt+1)*16;
            a0 = *(const float4*)(Ag + ko);
            a1 = *(const float4*)(Ag + ko + 4);
            b0 = *(const float4*)(Bg + ko);
            b1 = *(const float4*)(Bg + ko + 4);
        }
        #pragma unroll
        for (int kk=0; kk<16; kk++){
            float4 av0 = *(const float4*)&As[cur][kk][tm];
            float4 av1 = *(const float4*)&As[cur][kk][tm+4];
            ull bp0 = *(const ull*)&Bs[cur][kk][tn2];
            ull bp1 = *(const ull*)&Bs[cur][kk][tn2+32];
            ull bp2 = *(const ull*)&Bs[cur][kk][tn2+64];
            ull bp3 = *(const ull*)&Bs[cur][kk][tn2+96];
            float am[8] = {av0.x,av0.y,av0.z,av0.w,av1.x,av1.y,av1.z,av1.w};
            #pragma unroll
            for (int i=0;i<8;i++){
                ull as_ = splat2(am[i]);
                ffma2(acc[i][0], as_, bp0);
                ffma2(acc[i][1], as_, bp1);
                ffma2(acc[i][2], as_, bp2);
                ffma2(acc[i][3], as_, bp3);
            }
        }
        if (kt < 47){
            int nx = 1 - cur;
            As[nx][kqa+0][r]=a0.x; As[nx][kqa+1][r]=a0.y; As[nx][kqa+2][r]=a0.z; As[nx][kqa+3][r]=a0.w;
            As[nx][kqa+4][r]=a1.x; As[nx][kqa+5][r]=a1.y; As[nx][kqa+6][r]=a1.z; As[nx][kqa+7][r]=a1.w;
            Bs[nx][kqa+0][r]=b0.x; Bs[nx][kqa+1][r]=b0.y; Bs[nx][kqa+2][r]=b0.z; Bs[nx][kqa+3][r]=b0.w;
            Bs[nx][kqa+4][r]=b1.x; Bs[nx][kqa+5][r]=b1.y; Bs[nx][kqa+6][r]=b1.z; Bs[nx][kqa+7][r]=b1.w;
            __syncthreads();
        }
    }

    #pragma unroll
    for (int i=0;i<8;i++){
        float* crow = C + (size_t)(m0+tm+i)*G4 + n0;
        #pragma unroll
        for (int j=0;j<4;j++){
            float2 v = unpack2(acc[i][j]);
            v.x += bias[n0+tn2+32*j];
            v.y += bias[n0+tn2+32*j+1];
            *(float2*)(crow + tn2 + 32*j) = v;
        }
    }
}

// ---------------- persistent bidirectional LSTM ----------------
// R16 structure with the GLOBAL barrier dissolved into per-warp producer
// polling: warp w's 48 k-rows are produced by exactly 4 blocks (u=w*4..w*4+3),
// so each warp polls only those 4 flags and starts its GEMM immediately.
// Straggler delay is absorbed into other warps' compute; steps pipeline.
// Safety: a block's cell(s) transitively requires ALL 64 flags >= s (16 warps
// cover all producers), so no block runs >1 step ahead -> 2-buffer h is safe.
__global__ __launch_bounds__(512, 1) void k_lstm_pers(
    const float* __restrict__ Whf, const float* __restrict__ Whb)
{
    extern __shared__ float sm[];
    float* ws   = sm;                              // [768][48]     147456 B
    float* hb   = sm + HH*CPB;                     // 16 warps x 512 floats = 32768 B
    float* gred = hb + NW*512;                     // [8][32][50]    51200 B

    int tid = threadIdx.x;
    int bid = blockIdx.x;
    int d    = bid >> 6;
    int bid6 = bid & 63;
    int u0   = bid6 * UPB;
    const float* Wm = d ? Whb : Whf;
    int* flagd = g_flag[d];

    // stage weights: ws[k][c], c = g*UPB+uu
    for (int idx = tid; idx < CPB*(HH/4); idx += 512){
        int c  = idx / (HH/4);
        int kq = (idx % (HH/4)) * 4;
        int g = c / UPB, uu = c % UPB;
        float4 w = *(const float4*)(Wm + (size_t)(g*HH + u0 + uu)*HH + kq);
        ws[(kq+0)*CPB + c] = w.x;
        ws[(kq+1)*CPB + c] = w.y;
        ws[(kq+2)*CPB + c] = w.z;
        ws[(kq+3)*CPB + c] = w.w;
    }
    __syncthreads();

    int warp  = tid >> 5;
    int lane  = tid & 31;
    int mh    = lane >> 3;
    int mBase = mh * 8;
    int cBase = (lane & 7) * 6;

    float* hbw = hb + warp*512;               // 2 bufs x 8 rows x 32 floats
    int    kwq = warp*KPW*8;                  // warp k-base in float4 units
    int    wp4 = warp*4;                      // first producer block of this warp

    const float* xg_d = g_xg[d];
    int uu1 = tid >> 5, mm1 = tid & 31;       // cell pair (tid<384)
    float c1 = 0.f;
    int pairbar = (warp & 7) + 1;             // named barrier id for (w, w+8)

    for (int s = 0; s < WW; s++){
        int t = d ? (WW-1-s) : s;
        const float4* hs4 = (const float4*)(&g_hstate[s&1][d][0][0]) + kwq;
        float*        hdst = &g_hstate[(s+1)&1][d][0][0];

        // xg prefetch first: independent of producers, issues before polling
        float x1[4];
        if (tid < 384){
            const float* xb = xg_d + (size_t)(mm1*WW + t)*G4 + u0 + uu1;
            x1[0]=xb[0]; x1[1]=xb[HH]; x1[2]=xb[2*HH]; x1[3]=xb[3*HH];
        }

        // per-warp producer poll: wait until this warp's 4 producer blocks
        // have published h for step s (flag >= s). s=0 passes trivially.
        if (s > 0){
            while (true){
                int f = (lane < 4) ? ld_poll(&flagd[wp4 + lane]) : 0x7fffffff;
                if (__all_sync(0xffffffffu, f >= s)) break;
                __nanosleep(16);
            }
        }

        // stage sub-chunk 0 (warp-private; L1 bypass: h written by remote SMs)
        float4 p0 = __ldcg(hs4 + lane);
        float4 p1 = __ldcg(hs4 + lane + 32);
        ((float4*)hbw)[lane]      = p0;
        ((float4*)hbw)[lane + 32] = p1;
        __syncwarp();

        ull acc[8][3];
        #pragma unroll
        for (int mi=0;mi<8;mi++){ acc[mi][0]=0ull; acc[mi][1]=0ull; acc[mi][2]=0ull; }

        for (int sc=0; sc<NSC; sc++){
            int cur = sc & 1;
            if (sc < NSC-1){
                p0 = __ldcg(hs4 + (sc+1)*64 + lane);
                p1 = __ldcg(hs4 + (sc+1)*64 + lane + 32);
            }
            const float* hc = hbw + cur*256 + mBase;
            const float* wc = ws + (warp*KPW + sc*SC)*CPB + cBase;
            #pragma unroll
            for (int r=0; r<SC; r++){
                float4 h0 = *(const float4*)(hc + r*32);
                float4 h1 = *(const float4*)(hc + r*32 + 4);
                ull w0 = *(const ull*)(wc + r*CPB);
                ull w1 = *(const ull*)(wc + r*CPB + 2);
                ull w2 = *(const ull*)(wc + r*CPB + 4);
                ull a;
                a = splat2(h0.x); ffma2(acc[0][0],a,w0); ffma2(acc[0][1],a,w1); ffma2(acc[0][2],a,w2);
                a = splat2(h0.y); ffma2(acc[1][0],a,w0); ffma2(acc[1][1],a,w1); ffma2(acc[1][2],a,w2);
                a = splat2(h0.z); ffma2(acc[2][0],a,w0); ffma2(acc[2][1],a,w1); ffma2(acc[2][2],a,w2);
                a = splat2(h0.w); ffma2(acc[3][0],a,w0); ffma2(acc[3][1],a,w1); ffma2(acc[3][2],a,w2);
                a = splat2(h1.x); ffma2(acc[4][0],a,w0); ffma2(acc[4][1],a,w1); ffma2(acc[4][2],a,w2);
                a = splat2(h1.y); ffma2(acc[5][0],a,w0); ffma2(acc[5][1],a,w1); ffma2(acc[5][2],a,w2);
                a = splat2(h1.z); ffma2(acc[6][0],a,w0); ffma2(acc[6][1],a,w1); ffma2(acc[6][2],a,w2);
                a = splat2(h1.w); ffma2(acc[7][0],a,w0); ffma2(acc[7][1],a,w1); ffma2(acc[7][2],a,w2);
            }
            if (sc < NSC-1){
                int nx = 1 - cur;
                ((float4*)(hbw + nx*256))[lane]      = p0;
                ((float4*)(hbw + nx*256))[lane + 32] = p1;
            }
            __syncwarp();
        }

        // reduction phase 1: warps 8-15 dump partials to gred[warp-8]
        if (warp >= 8){
            float* gr = gred + (warp-8)*GWSZ + mBase*GPITCH + cBase;
            #pragma unroll
            for (int mi=0;mi<8;mi++){
                float* row = gr + mi*GPITCH;
                *(float2*)(row    ) = unpack2(acc[mi][0]);
                *(float2*)(row + 2) = unpack2(acc[mi][1]);
                *(float2*)(row + 4) = unpack2(acc[mi][2]);
            }
        }
        // pairwise handoff: warp w <-> warp w+8 only (64-thread named barrier)
        asm volatile("bar.sync %0, 64;" :: "r"(pairbar) : "memory");

        // phase 2: warps 0-7 fold partner (warp+8) partials, dump 2-way sums
        if (warp < 8){
            float* gr = gred + warp*GWSZ + mBase*GPITCH + cBase;
            #pragma unroll
            for (int mi=0;mi<8;mi++){
                float* row = gr + mi*GPITCH;
                ull v0 = add2(acc[mi][0], *(const ull*)(row    ));
                ull v1 = add2(acc[mi][1], *(const ull*)(row + 2));
                ull v2 = add2(acc[mi][2], *(const ull*)(row + 4));
                *(float2*)(row    ) = unpack2(v0);
                *(float2*)(row + 2) = unpack2(v1);
                *(float2*)(row + 4) = unpack2(v2);
            }
        }
        __syncthreads();

        // LSTM cell: sum 8 slots + xg; fast EX2-based transcendentals
        float hval = 0.f;
        if (tid < 384){
            int base = mm1*GPITCH + uu1;
            float gi=x1[0], gf=x1[1], gg=x1[2], go=x1[3];
            #pragma unroll
            for (int w=0; w<8; w++){
                const float* g = gred + w*GWSZ + base;
                gi += g[0]; gf += g[UPB]; gg += g[2*UPB]; go += g[3*UPB];
            }
            float cn = fsig(gf)*c1 + fsig(gi)*ftanh_(gg);
            hval = fsig(go)*ftanh_(cn);
            c1 = cn;
            hdst[(u0+uu1)*BB + mm1] = hval;
        }

        // writer-side fence + block sync, then publish flag = s+1
        __threadfence();
        __syncthreads();
        if (tid == 0) atomicExch(&flagd[bid6], s+1);

        // g_hs history store off the critical path (read only by k_final)
        if (tid < 384)
            g_hs[d][(size_t)(mm1*WW + t)*HH + u0 + uu1] = hval;
        // no end-of-step barrier: next iteration's per-warp poll gates staging
    }
}

// ---------------- final: logits, softmax, argmax ----------------
__global__ void k_final(const float* __restrict__ Wl, const float* __restrict__ bl,
                        float* __restrict__ out, int out_size)
{
    int p    = blockIdx.x*(blockDim.x>>5) + (threadIdx.x>>5);
    int lane = threadIdx.x & 31;
    if (p >= MR) return;

    const float* hf = g_hs[0] + (size_t)p*HH;
    const float* hb = g_hs[1] + (size_t)p*HH;

    float lg[NNER];
    #pragma unroll
    for (int n=0;n<NNER;n++) lg[n]=0.f;

    for (int k=lane; k<HH; k+=32){
        float hv  = hf[k];
        float hv2 = hb[k];
        #pragma unroll
        for (int n=0;n<NNER;n++){
            lg[n] += Wl[n*2*HH + k]*hv + Wl[n*2*HH + HH + k]*hv2;
        }
    }
    #pragma unroll
    for (int n=0;n<NNER;n++){
        #pragma unroll
        for (int o=16;o;o>>=1) lg[n] += __shfl_xor_sync(0xffffffffu, lg[n], o);
    }
    if (lane==0){
        float mx = -1e30f;
        #pragma unroll
        for (int n=0;n<NNER;n++){ lg[n] += bl[n]; mx = fmaxf(mx, lg[n]); }
        float e[NNER], sum=0.f;
        #pragma unroll
        for (int n=0;n<NNER;n++){ e[n] = __expf(lg[n]-mx); sum += e[n]; }
        float inv = __fdividef(1.0f, sum);
        int best = 0; float bv = lg[0];
        #pragma unroll
        for (int n=1;n<NNER;n++){ if (lg[n] > bv){ bv = lg[n]; best = n; } }
        #pragma unroll
        for (int n=0;n<NNER;n++) out[p*NNER + n] = e[n]*inv;
        if (out_size >= MR*NNER + MR) out[MR*NNER + p] = (float)best;
    }
}

// ---------------- launch ----------------
extern "C" void kernel_launch(void* const* d_in, const int* in_sizes, int n_in,
                              void* d_out, int out_size)
{
    const float* bert = (const float*)d_in[0];
    const int*   wid  = (const int*)  d_in[1];
    const float* Wihf = (const float*)d_in[2];
    const float* Whhf = (const float*)d_in[3];
    const float* bf   = (const float*)d_in[4];
    const float* Wihb = (const float*)d_in[5];
    const float* Whhb = (const float*)d_in[6];
    const float* bbv  = (const float*)d_in[7];
    const float* Wlin = (const float*)d_in[8];
    const float* blin = (const float*)d_in[9];

    static int smem_set = 0;
    const int pers_smem = (HH*CPB)*4 + NW*512*4 + (8*GWSZ)*4;  // 231424 B
    if (!smem_set){
        cudaFuncSetAttribute(k_lstm_pers, cudaFuncAttributeMaxDynamicSharedMemorySize, pers_smem);
        smem_set = 1;
    }

    k_init<<<128, 256>>>();
    k_find<<<(BB*TT + 255)/256, 256>>>(wid);
    k_gather<<<MR, 192>>>(bert);
    k_gemm_xg<<<dim3(G4/128, MPAD/128, 2), 256>>>(Wihf, Wihb, bf, bbv);
    k_lstm_pers<<<NBLK, 512, pers_smem>>>(Whhf, Whhb);
    k_final<<<(MR + 3)/4, 128>>>(Wlin, blin, (float*)d_out, out_size);
}